// round 11
// baseline (speedup 1.0000x reference)
#include <cuda_runtime.h>
#include <math.h>

// Problem constants
#define BB 16
#define CC 48
#define TT 96
#define PATCH 12
#define STEPS 7
#define FF 64
#define ALPHA 0.5f
#define EPS 1e-5f
#define NFEAT (CC*TT)    // 4608
#define CP (CC*PATCH)    // 576
#define SPLIT 3
#define ROWS (CC/SPLIT)  // 16

// Scratch (allocation-free rule: __device__ globals)
__device__ float d_xn[BB*NFEAT];
__device__ float d_resbuf[BB*CP];
__device__ float d_tbuf[BB*CP];

// ---------------------------------------------------------------------------
// f32x2 packed helpers (sm_103a)
// ---------------------------------------------------------------------------
typedef unsigned long long ull;

__device__ __forceinline__ ull pk2(float lo, float hi) {
    ull r; asm("mov.b64 %0, {%1, %2};" : "=l"(r) : "f"(lo), "f"(hi)); return r;
}
__device__ __forceinline__ void upk2(ull v, float& lo, float& hi) {
    asm("mov.b64 {%0, %1}, %2;" : "=f"(lo), "=f"(hi) : "l"(v));
}
__device__ __forceinline__ ull fma2(ull a, ull b, ull c) {
    ull d; asm("fma.rn.f32x2 %0, %1, %2, %3;" : "=l"(d) : "l"(a), "l"(b), "l"(c)); return d;
}
__device__ __forceinline__ ull mul2(ull a, ull b) {
    ull d; asm("mul.rn.f32x2 %0, %1, %2;" : "=l"(d) : "l"(a), "l"(b)); return d;
}
__device__ __forceinline__ ull add2(ull a, ull b) {
    ull d; asm("add.rn.f32x2 %0, %1, %2;" : "=l"(d) : "l"(a), "l"(b)); return d;
}
__device__ __forceinline__ float ex2f(float x) {
    float r; asm("ex2.approx.f32 %0, %1;" : "=f"(r) : "f"(x)); return r;
}
__device__ __forceinline__ float rcpf(float x) {
    float r; asm("rcp.approx.f32 %0, %1;" : "=f"(r) : "f"(x)); return r;
}

__device__ __forceinline__ float gelu_exact(float v) {
    return 0.5f * v * (1.0f + erff(v * 0.70710678118654752f));
}

// ---------------------------------------------------------------------------
// Kernel 0: BatchNorm over batch for all C*T features; writes xn and first
// patch directly into d_out.
// ---------------------------------------------------------------------------
__global__ void bn0_kernel(const float* __restrict__ x,
                           const float* __restrict__ g0,
                           const float* __restrict__ b0,
                           float* __restrict__ out)
{
    int f = blockIdx.x * blockDim.x + threadIdx.x;
    if (f >= NFEAT) return;
    float v[BB];
    float sum = 0.f;
    #pragma unroll
    for (int b = 0; b < BB; b++) { v[b] = x[b*NFEAT + f]; sum += v[b]; }
    float mu = sum * (1.0f/BB);
    float var = 0.f;
    #pragma unroll
    for (int b = 0; b < BB; b++) { float d = v[b] - mu; var = fmaf(d, d, var); }
    var *= (1.0f/BB);
    float rs = rsqrtf(var + EPS);
    float g = g0[f], bb0 = b0[f];
    int t = f % TT;
    #pragma unroll
    for (int b = 0; b < BB; b++) {
        float y = (v[b] - mu) * rs * g + bb0;
        d_xn[b*NFEAT + f] = y;
        if (t < PATCH) out[b*NFEAT + f] = y;
    }
}

// ---------------------------------------------------------------------------
// Step kernel A: per channel c — BN1(prev) -> Wagg matmul + gelu -> +xw ->
// BN2 -> t,msg,res. Shuffle-based BN: tid = p*16 + b; reductions over the
// 16-lane b-group via shfl_xor. One __syncthreads.
// grid = 48 blocks, 192 threads.
// ---------------------------------------------------------------------------
__global__ __launch_bounds__(192) void stepA_kernel(
    const float* __restrict__ out,
    const float* __restrict__ g1, const float* __restrict__ b1,
    const float* __restrict__ g2, const float* __restrict__ b2,
    const float* __restrict__ Wagg, const float* __restrict__ bagg,
    int s)
{
    int c = blockIdx.x;
    int tid = threadIdx.x;
    int p = tid >> 4;        // 0..11
    int b = tid & 15;        // 0..15

    __shared__ float sBn[PATCH*16];   // bn1 output [p][b]

    // load prev value for (b, c, 12s+p)
    float v = out[b*NFEAT + c*TT + 12*s + p];

    // BN1 over b (16-lane group)
    float sum = v;
    #pragma unroll
    for (int m = 1; m < 16; m <<= 1) sum += __shfl_xor_sync(0xffffffffu, sum, m);
    float mu = sum * (1.0f/16.0f);
    float d = v - mu;
    float q = d * d;
    #pragma unroll
    for (int m = 1; m < 16; m <<= 1) q += __shfl_xor_sync(0xffffffffu, q, m);
    float rs = rsqrtf(q * (1.0f/16.0f) + EPS);
    float bn = d * rs * g1[c*PATCH + p] + b1[c*PATCH + p];
    sBn[p*16 + b] = bn;
    __syncthreads();

    // matmul row q=p for batch b: inp = gelu(sum_pp bn[pp][b]*Wagg[p][pp] + bagg[p])
    float acc = bagg[p];
    #pragma unroll
    for (int pp = 0; pp < PATCH; pp++)
        acc = fmaf(sBn[pp*16 + b], Wagg[p*PATCH + pp], acc);
    float inp = gelu_exact(acc);
    float res = inp + d_xn[b*NFEAT + c*TT + 12*s + PATCH + p];

    // BN2 over b (same lane group; feature = (c,p))
    float sum2 = res;
    #pragma unroll
    for (int m = 1; m < 16; m <<= 1) sum2 += __shfl_xor_sync(0xffffffffu, sum2, m);
    float mu2 = sum2 * (1.0f/16.0f);
    float d2 = res - mu2;
    float q2 = d2 * d2;
    #pragma unroll
    for (int m = 1; m < 16; m <<= 1) q2 += __shfl_xor_sync(0xffffffffu, q2, m);
    float rs2 = rsqrtf(q2 * (1.0f/16.0f) + EPS);
    float tv = d2 * rs2 * g2[c*PATCH + p] + b2[c*PATCH + p];

    d_tbuf[b*CP + c*PATCH + p] = tv;
    d_resbuf[b*CP + c*PATCH + p] = res;
}

// ---------------------------------------------------------------------------
// Step kernel B: edge MLP + top-3 + softmax + aggregation.
// grid = 576 (= 192 (b,p) x 3 segs), 192 threads.
// GELU via Abramowitz-Stegun 7.1.26 erf (max err 1.5e-7), evaluated in
// packed f32x2 (2 evals per op) with scalar MUFU EX2/RCP.
//   u = a/sqrt(2);  gelu(a)*W2 = w2' * ((u+|u|) - |u|*t*P(t)*e^{-u^2})
// where t = 1/(1 + 0.3275911|u|), w2' = W2*sqrt(2)/2, and W1/bm1 pre-scaled
// by 1/sqrt(2).
// ---------------------------------------------------------------------------
#define INVR2 0.70710678118654752f

__global__ __launch_bounds__(192) void stepB_kernel(
    float* __restrict__ out,
    const float* __restrict__ W1, const float* __restrict__ bm1,
    const float* __restrict__ W2, const float* __restrict__ bm2,
    const float* __restrict__ wmsg, const float* __restrict__ bmsg,
    int s)
{
    int blk = blockIdx.x;
    int bp  = blk / SPLIT;
    int seg = blk % SPLIT;
    int b = bp / PATCH;
    int p = bp % PATCH;
    int tid = threadIdx.x;

    __shared__ float  sT[CC], sMsg[CC], sRes[CC];
    __shared__ ull    sWx2[FF];     // {wx', wx'}
    __shared__ ull    sW22[FF];     // {w2', w2'}
    __shared__ float2 sWyz[FF];     // {wy', bm1'}
    __shared__ float  sE[ROWS*CC];  // 768

    if (tid < CC) {
        float tv = d_tbuf[b*CP + tid*PATCH + p];
        sT[tid]   = tv;
        sMsg[tid] = fmaf(tv, wmsg[0], bmsg[0]);
        sRes[tid] = d_resbuf[b*CP + tid*PATCH + p];
    }
    if (tid >= 64 && tid < 128) {
        int f = tid - 64;
        float wx = W1[2*f]   * INVR2;
        float wy = W1[2*f+1] * INVR2;
        float wb = bm1[f]    * INVR2;
        float w2 = W2[f]     * INVR2;
        sWx2[f] = pk2(wx, wx);
        sW22[f] = pk2(w2, w2);
        sWyz[f] = make_float2(wy, wb);
    }
    __syncthreads();

    // packed constants
    const ull ABSM  = 0x7FFFFFFF7FFFFFFFULL;
    const ull NL2E  = pk2(-1.442695041f, -1.442695041f);
    const ull PC    = pk2(0.3275911f, 0.3275911f);
    const ull ONE2  = pk2(1.0f, 1.0f);
    // negated A&S coefficients (Horner from a5 down)
    const ull N5 = pk2(-1.061405429f, -1.061405429f);
    const ull N4 = pk2( 1.453152027f,  1.453152027f);
    const ull N3 = pk2(-1.421413741f, -1.421413741f);
    const ull N2 = pk2( 0.284496736f,  0.284496736f);
    const ull N1 = pk2(-0.254829592f, -0.254829592f);

    float zjv = sT[tid % CC];
    int rbase = tid / CC;            // 0..3
    float bm2v = bm2[0];

    // rows: i_u = seg*16 + rbase + 4u ; pack (u0,u1) and (u2,u3)
    ull zi01 = pk2(sT[seg*ROWS + rbase],     sT[seg*ROWS + rbase + 4]);
    ull zi23 = pk2(sT[seg*ROWS + rbase + 8], sT[seg*ROWS + rbase + 12]);
    ull acc01 = pk2(bm2v, bm2v);
    ull acc23 = acc01;

    #pragma unroll 8
    for (int f = 0; f < FF; f++) {
        ull   wx = sWx2[f];
        ull   w2 = sW22[f];
        float2 yz = sWyz[f];
        float v = fmaf(yz.x, zjv, yz.y);
        ull vv = pk2(v, v);

        #pragma unroll
        for (int half = 0; half < 2; half++) {
            ull zi  = half ? zi23  : zi01;
            ull u   = fma2(wx, zi, vv);
            ull ax  = u & ABSM;
            ull x2  = mul2(u, u);
            ull arg = mul2(x2, NL2E);
            float a0, a1; upk2(arg, a0, a1);
            float E0 = ex2f(a0), E1 = ex2f(a1);
            ull dpk = fma2(PC, ax, ONE2);
            float d0, d1; upk2(dpk, d0, d1);
            ull t = pk2(rcpf(d0), rcpf(d1));
            // h = -(a1 + t(a2 + t(a3 + t(a4 + t*a5))))
            ull h = fma2(N5, t, N4);
            h = fma2(h, t, N3);
            h = fma2(h, t, N2);
            h = fma2(h, t, N1);
            ull at = mul2(ax, t);
            ull r  = mul2(at, h);          // = -|u|*t*P(t)
            ull upa = add2(u, ax);         // u + |u|
            ull Ep = pk2(E0, E1);
            ull g  = fma2(r, Ep, upa);     // u + u*erf(u)
            if (half) acc23 = fma2(w2, g, acc23);
            else      acc01 = fma2(w2, g, acc01);
        }
    }

    {
        float e0, e1, e2, e3;
        upk2(acc01, e0, e1);
        upk2(acc23, e2, e3);
        int j = tid % CC;
        sE[(rbase     )*CC + j] = e0;
        sE[(rbase +  4)*CC + j] = e1;
        sE[(rbase +  8)*CC + j] = e2;
        sE[(rbase + 12)*CC + j] = e3;
    }
    __syncthreads();

    // top-3 + softmax + aggregate: one thread per row
    if (tid < ROWS) {
        int i = seg*ROWS + tid;
        const float* row = &sE[tid*CC];
        float v0 = -1e30f, v1 = -1e30f, v2 = -1e30f;
        int   i0 = 0,      i1 = 0,      i2 = 0;
        #pragma unroll 4
        for (int j = 0; j < CC; j++) {
            float e = row[j];
            if (e > v0)      { v2=v1; i2=i1; v1=v0; i1=i0; v0=e; i0=j; }
            else if (e > v1) { v2=v1; i2=i1; v1=e;  i1=j; }
            else if (e > v2) { v2=e;  i2=j; }
        }
        float e1 = expf(v1 - v0), e2 = expf(v2 - v0);
        float inv = 1.0f / (1.0f + e1 + e2);
        float zn = (sMsg[i0] + e1*sMsg[i1] + e2*sMsg[i2]) * inv;
        float o = sRes[i] + ALPHA * zn;
        out[b*NFEAT + i*TT + 12*s + PATCH + p] = o;   // prev for step s+1
    }
}

// ---------------------------------------------------------------------------
extern "C" void kernel_launch(void* const* d_in, const int* in_sizes, int n_in,
                              void* d_out, int out_size)
{
    const float* x    = (const float*)d_in[0];
    const float* g0   = (const float*)d_in[1];
    const float* b0   = (const float*)d_in[2];
    const float* g1   = (const float*)d_in[3];
    const float* b1   = (const float*)d_in[4];
    const float* g2   = (const float*)d_in[5];
    const float* b2   = (const float*)d_in[6];
    const float* Wagg = (const float*)d_in[7];
    const float* bagg = (const float*)d_in[8];
    const float* W1   = (const float*)d_in[9];
    const float* bm1  = (const float*)d_in[10];
    const float* W2   = (const float*)d_in[11];
    const float* bm2  = (const float*)d_in[12];
    const float* wmsg = (const float*)d_in[13];
    const float* bmsg = (const float*)d_in[14];
    float* out = (float*)d_out;

    bn0_kernel<<<(NFEAT + 255)/256, 256>>>(x, g0, b0, out);

    for (int s = 0; s < STEPS; s++) {
        stepA_kernel<<<CC, 192>>>(out, g1, b1, g2, b2, Wagg, bagg, s);
        stepB_kernel<<<BB*PATCH*SPLIT, 192>>>(out, W1, bm1, W2, bm2,
                                              wmsg, bmsg, s);
    }
}

// round 12
// speedup vs baseline: 1.0011x; 1.0011x over previous
#include <cuda_runtime.h>
#include <math.h>

// Problem constants
#define BB 16
#define CC 48
#define TT 96
#define PATCH 12
#define STEPS 7
#define FF 64
#define ALPHA 0.5f
#define EPS 1e-5f
#define NFEAT (CC*TT)    // 4608
#define CP (CC*PATCH)    // 576
#define SPLIT 3
#define ROWS (CC/SPLIT)  // 16

// Scratch (allocation-free rule: __device__ globals)
__device__ float d_xn[BB*NFEAT];
__device__ float d_resbuf[BB*CP];
__device__ float d_tbuf[BB*CP];

// ---------------------------------------------------------------------------
// f32x2 packed helpers (sm_103a)
// ---------------------------------------------------------------------------
typedef unsigned long long ull;

__device__ __forceinline__ ull pk2(float lo, float hi) {
    ull r; asm("mov.b64 %0, {%1, %2};" : "=l"(r) : "f"(lo), "f"(hi)); return r;
}
__device__ __forceinline__ void upk2(ull v, float& lo, float& hi) {
    asm("mov.b64 {%0, %1}, %2;" : "=f"(lo), "=f"(hi) : "l"(v));
}
__device__ __forceinline__ ull fma2(ull a, ull b, ull c) {
    ull d; asm("fma.rn.f32x2 %0, %1, %2, %3;" : "=l"(d) : "l"(a), "l"(b), "l"(c)); return d;
}
__device__ __forceinline__ ull mul2(ull a, ull b) {
    ull d; asm("mul.rn.f32x2 %0, %1, %2;" : "=l"(d) : "l"(a), "l"(b)); return d;
}
__device__ __forceinline__ ull add2(ull a, ull b) {
    ull d; asm("add.rn.f32x2 %0, %1, %2;" : "=l"(d) : "l"(a), "l"(b)); return d;
}
__device__ __forceinline__ float ex2f(float x) {
    float r; asm("ex2.approx.f32 %0, %1;" : "=f"(r) : "f"(x)); return r;
}
__device__ __forceinline__ float rcpf(float x) {
    float r; asm("rcp.approx.f32 %0, %1;" : "=f"(r) : "f"(x)); return r;
}

__device__ __forceinline__ float gelu_exact(float v) {
    return 0.5f * v * (1.0f + erff(v * 0.70710678118654752f));
}

// ---------------------------------------------------------------------------
// Kernel 0: BatchNorm over batch for all C*T features; writes xn and first
// patch directly into d_out.
// ---------------------------------------------------------------------------
__global__ void bn0_kernel(const float* __restrict__ x,
                           const float* __restrict__ g0,
                           const float* __restrict__ b0,
                           float* __restrict__ out)
{
    int f = blockIdx.x * blockDim.x + threadIdx.x;
    if (f >= NFEAT) return;
    float v[BB];
    float sum = 0.f;
    #pragma unroll
    for (int b = 0; b < BB; b++) { v[b] = x[b*NFEAT + f]; sum += v[b]; }
    float mu = sum * (1.0f/BB);
    float var = 0.f;
    #pragma unroll
    for (int b = 0; b < BB; b++) { float d = v[b] - mu; var = fmaf(d, d, var); }
    var *= (1.0f/BB);
    float rs = rsqrtf(var + EPS);
    float g = g0[f], bb0 = b0[f];
    int t = f % TT;
    #pragma unroll
    for (int b = 0; b < BB; b++) {
        float y = (v[b] - mu) * rs * g + bb0;
        d_xn[b*NFEAT + f] = y;
        if (t < PATCH) out[b*NFEAT + f] = y;
    }
}

// ---------------------------------------------------------------------------
// Step kernel A: per channel c — BN1(prev) -> Wagg matmul + gelu -> +xw ->
// BN2 -> t,msg,res. Shuffle-based BN: tid = p*16 + b; reductions over the
// 16-lane b-group via shfl_xor. One __syncthreads.
// grid = 48 blocks, 192 threads.
// ---------------------------------------------------------------------------
__global__ __launch_bounds__(192) void stepA_kernel(
    const float* __restrict__ out,
    const float* __restrict__ g1, const float* __restrict__ b1,
    const float* __restrict__ g2, const float* __restrict__ b2,
    const float* __restrict__ Wagg, const float* __restrict__ bagg,
    int s)
{
    int c = blockIdx.x;
    int tid = threadIdx.x;
    int p = tid >> 4;        // 0..11
    int b = tid & 15;        // 0..15

    __shared__ float sBn[PATCH*16];   // bn1 output [p][b]

    // load prev value for (b, c, 12s+p)
    float v = out[b*NFEAT + c*TT + 12*s + p];

    // BN1 over b (16-lane group)
    float sum = v;
    #pragma unroll
    for (int m = 1; m < 16; m <<= 1) sum += __shfl_xor_sync(0xffffffffu, sum, m);
    float mu = sum * (1.0f/16.0f);
    float d = v - mu;
    float q = d * d;
    #pragma unroll
    for (int m = 1; m < 16; m <<= 1) q += __shfl_xor_sync(0xffffffffu, q, m);
    float rs = rsqrtf(q * (1.0f/16.0f) + EPS);
    float bn = d * rs * g1[c*PATCH + p] + b1[c*PATCH + p];
    sBn[p*16 + b] = bn;
    __syncthreads();

    // matmul row q=p for batch b: inp = gelu(sum_pp bn[pp][b]*Wagg[p][pp] + bagg[p])
    float acc = bagg[p];
    #pragma unroll
    for (int pp = 0; pp < PATCH; pp++)
        acc = fmaf(sBn[pp*16 + b], Wagg[p*PATCH + pp], acc);
    float inp = gelu_exact(acc);
    float res = inp + d_xn[b*NFEAT + c*TT + 12*s + PATCH + p];

    // BN2 over b (same lane group; feature = (c,p))
    float sum2 = res;
    #pragma unroll
    for (int m = 1; m < 16; m <<= 1) sum2 += __shfl_xor_sync(0xffffffffu, sum2, m);
    float mu2 = sum2 * (1.0f/16.0f);
    float d2 = res - mu2;
    float q2 = d2 * d2;
    #pragma unroll
    for (int m = 1; m < 16; m <<= 1) q2 += __shfl_xor_sync(0xffffffffu, q2, m);
    float rs2 = rsqrtf(q2 * (1.0f/16.0f) + EPS);
    float tv = d2 * rs2 * g2[c*PATCH + p] + b2[c*PATCH + p];

    d_tbuf[b*CP + c*PATCH + p] = tv;
    d_resbuf[b*CP + c*PATCH + p] = res;
}

// ---------------------------------------------------------------------------
// Step kernel B: edge MLP + top-3 + softmax + aggregation.
// grid = 576 (= 192 (b,p) x 3 segs), 192 threads.
// GELU via Abramowitz-Stegun 7.1.26 erf (max err 1.5e-7), evaluated in
// packed f32x2 (2 evals per op) with scalar MUFU EX2/RCP.
//   u = a/sqrt(2);  gelu(a)*W2 = w2' * ((u+|u|) - |u|*t*P(t)*e^{-u^2})
// where t = 1/(1 + 0.3275911|u|), w2' = W2*sqrt(2)/2, and W1/bm1 pre-scaled
// by 1/sqrt(2).
// ---------------------------------------------------------------------------
#define INVR2 0.70710678118654752f

__global__ __launch_bounds__(192) void stepB_kernel(
    float* __restrict__ out,
    const float* __restrict__ W1, const float* __restrict__ bm1,
    const float* __restrict__ W2, const float* __restrict__ bm2,
    const float* __restrict__ wmsg, const float* __restrict__ bmsg,
    int s)
{
    int blk = blockIdx.x;
    int bp  = blk / SPLIT;
    int seg = blk % SPLIT;
    int b = bp / PATCH;
    int p = bp % PATCH;
    int tid = threadIdx.x;

    __shared__ float  sT[CC], sMsg[CC], sRes[CC];
    __shared__ ull    sWx2[FF];     // {wx', wx'}
    __shared__ ull    sW22[FF];     // {w2', w2'}
    __shared__ float2 sWyz[FF];     // {wy', bm1'}
    __shared__ float  sE[ROWS*CC];  // 768

    if (tid < CC) {
        float tv = d_tbuf[b*CP + tid*PATCH + p];
        sT[tid]   = tv;
        sMsg[tid] = fmaf(tv, wmsg[0], bmsg[0]);
        sRes[tid] = d_resbuf[b*CP + tid*PATCH + p];
    }
    if (tid >= 64 && tid < 128) {
        int f = tid - 64;
        float wx = W1[2*f]   * INVR2;
        float wy = W1[2*f+1] * INVR2;
        float wb = bm1[f]    * INVR2;
        float w2 = W2[f]     * INVR2;
        sWx2[f] = pk2(wx, wx);
        sW22[f] = pk2(w2, w2);
        sWyz[f] = make_float2(wy, wb);
    }
    __syncthreads();

    // packed constants
    const ull ABSM  = 0x7FFFFFFF7FFFFFFFULL;
    const ull NL2E  = pk2(-1.442695041f, -1.442695041f);
    const ull PC    = pk2(0.3275911f, 0.3275911f);
    const ull ONE2  = pk2(1.0f, 1.0f);
    // negated A&S coefficients (Horner from a5 down)
    const ull N5 = pk2(-1.061405429f, -1.061405429f);
    const ull N4 = pk2( 1.453152027f,  1.453152027f);
    const ull N3 = pk2(-1.421413741f, -1.421413741f);
    const ull N2 = pk2( 0.284496736f,  0.284496736f);
    const ull N1 = pk2(-0.254829592f, -0.254829592f);

    float zjv = sT[tid % CC];
    int rbase = tid / CC;            // 0..3
    float bm2v = bm2[0];

    // rows: i_u = seg*16 + rbase + 4u ; pack (u0,u1) and (u2,u3)
    ull zi01 = pk2(sT[seg*ROWS + rbase],     sT[seg*ROWS + rbase + 4]);
    ull zi23 = pk2(sT[seg*ROWS + rbase + 8], sT[seg*ROWS + rbase + 12]);
    ull acc01 = pk2(bm2v, bm2v);
    ull acc23 = acc01;

    #pragma unroll 8
    for (int f = 0; f < FF; f++) {
        ull   wx = sWx2[f];
        ull   w2 = sW22[f];
        float2 yz = sWyz[f];
        float v = fmaf(yz.x, zjv, yz.y);
        ull vv = pk2(v, v);

        #pragma unroll
        for (int half = 0; half < 2; half++) {
            ull zi  = half ? zi23  : zi01;
            ull u   = fma2(wx, zi, vv);
            ull ax  = u & ABSM;
            ull x2  = mul2(u, u);
            ull arg = mul2(x2, NL2E);
            float a0, a1; upk2(arg, a0, a1);
            float E0 = ex2f(a0), E1 = ex2f(a1);
            ull dpk = fma2(PC, ax, ONE2);
            float d0, d1; upk2(dpk, d0, d1);
            ull t = pk2(rcpf(d0), rcpf(d1));
            // h = -(a1 + t(a2 + t(a3 + t(a4 + t*a5))))
            ull h = fma2(N5, t, N4);
            h = fma2(h, t, N3);
            h = fma2(h, t, N2);
            h = fma2(h, t, N1);
            ull at = mul2(ax, t);
            ull r  = mul2(at, h);          // = -|u|*t*P(t)
            ull upa = add2(u, ax);         // u + |u|
            ull Ep = pk2(E0, E1);
            ull g  = fma2(r, Ep, upa);     // u + u*erf(u)
            if (half) acc23 = fma2(w2, g, acc23);
            else      acc01 = fma2(w2, g, acc01);
        }
    }

    {
        float e0, e1, e2, e3;
        upk2(acc01, e0, e1);
        upk2(acc23, e2, e3);
        int j = tid % CC;
        sE[(rbase     )*CC + j] = e0;
        sE[(rbase +  4)*CC + j] = e1;
        sE[(rbase +  8)*CC + j] = e2;
        sE[(rbase + 12)*CC + j] = e3;
    }
    __syncthreads();

    // top-3 + softmax + aggregate: one thread per row
    if (tid < ROWS) {
        int i = seg*ROWS + tid;
        const float* row = &sE[tid*CC];
        float v0 = -1e30f, v1 = -1e30f, v2 = -1e30f;
        int   i0 = 0,      i1 = 0,      i2 = 0;
        #pragma unroll 4
        for (int j = 0; j < CC; j++) {
            float e = row[j];
            if (e > v0)      { v2=v1; i2=i1; v1=v0; i1=i0; v0=e; i0=j; }
            else if (e > v1) { v2=v1; i2=i1; v1=e;  i1=j; }
            else if (e > v2) { v2=e;  i2=j; }
        }
        float e1 = expf(v1 - v0), e2 = expf(v2 - v0);
        float inv = 1.0f / (1.0f + e1 + e2);
        float zn = (sMsg[i0] + e1*sMsg[i1] + e2*sMsg[i2]) * inv;
        float o = sRes[i] + ALPHA * zn;
        out[b*NFEAT + i*TT + 12*s + PATCH + p] = o;   // prev for step s+1
    }
}

// ---------------------------------------------------------------------------
extern "C" void kernel_launch(void* const* d_in, const int* in_sizes, int n_in,
                              void* d_out, int out_size)
{
    const float* x    = (const float*)d_in[0];
    const float* g0   = (const float*)d_in[1];
    const float* b0   = (const float*)d_in[2];
    const float* g1   = (const float*)d_in[3];
    const float* b1   = (const float*)d_in[4];
    const float* g2   = (const float*)d_in[5];
    const float* b2   = (const float*)d_in[6];
    const float* Wagg = (const float*)d_in[7];
    const float* bagg = (const float*)d_in[8];
    const float* W1   = (const float*)d_in[9];
    const float* bm1  = (const float*)d_in[10];
    const float* W2   = (const float*)d_in[11];
    const float* bm2  = (const float*)d_in[12];
    const float* wmsg = (const float*)d_in[13];
    const float* bmsg = (const float*)d_in[14];
    float* out = (float*)d_out;

    bn0_kernel<<<(NFEAT + 255)/256, 256>>>(x, g0, b0, out);

    for (int s = 0; s < STEPS; s++) {
        stepA_kernel<<<CC, 192>>>(out, g1, b1, g2, b2, Wagg, bagg, s);
        stepB_kernel<<<BB*PATCH*SPLIT, 192>>>(out, W1, bm1, W2, bm2,
                                              wmsg, bmsg, s);
    }
}

// round 13
// speedup vs baseline: 1.0589x; 1.0577x over previous
#include <cuda_runtime.h>
#include <math.h>

// Problem constants
#define BB 16
#define CC 48
#define TT 96
#define PATCH 12
#define STEPS 7
#define FF 64
#define ALPHA 0.5f
#define EPS 1e-5f
#define NFEAT (CC*TT)    // 4608
#define CP (CC*PATCH)    // 576
#define SPLIT 3
#define ROWS (CC/SPLIT)  // 16
#define NBLK (BB*PATCH*SPLIT)  // 576
#define NPROD CC               // 48 producer blocks

// Scratch (allocation-free rule: __device__ globals)
__device__ float d_xn[BB*NFEAT];
__device__ float d_resbuf[BB*CP];
__device__ float d_tbuf[BB*CP];
__device__ unsigned int d_ctr[STEPS];

// ---------------------------------------------------------------------------
// f32x2 packed helpers (sm_103a)
// ---------------------------------------------------------------------------
typedef unsigned long long ull;

__device__ __forceinline__ ull pk2(float lo, float hi) {
    ull r; asm("mov.b64 %0, {%1, %2};" : "=l"(r) : "f"(lo), "f"(hi)); return r;
}
__device__ __forceinline__ void upk2(ull v, float& lo, float& hi) {
    asm("mov.b64 {%0, %1}, %2;" : "=f"(lo), "=f"(hi) : "l"(v));
}
__device__ __forceinline__ ull fma2(ull a, ull b, ull c) {
    ull d; asm("fma.rn.f32x2 %0, %1, %2, %3;" : "=l"(d) : "l"(a), "l"(b), "l"(c)); return d;
}
__device__ __forceinline__ ull mul2(ull a, ull b) {
    ull d; asm("mul.rn.f32x2 %0, %1, %2;" : "=l"(d) : "l"(a), "l"(b)); return d;
}
__device__ __forceinline__ ull add2(ull a, ull b) {
    ull d; asm("add.rn.f32x2 %0, %1, %2;" : "=l"(d) : "l"(a), "l"(b)); return d;
}
__device__ __forceinline__ float rcpf(float x) {
    float r; asm("rcp.approx.f32 %0, %1;" : "=f"(r) : "f"(x)); return r;
}

__device__ __forceinline__ float gelu_exact(float v) {
    return 0.5f * v * (1.0f + erff(v * 0.70710678118654752f));
}

// A&S 7.1.28: erf(x) = 1 - (1 + a1 x + ... + a6 x^6)^-16, x>=0, |eps|<=3e-7.
// Returns g = u*(1+erf(u)) = (u+|u|) - |u|*z^-16 for packed pair u.
__device__ __forceinline__ ull edge_gelu2(ull wx, ull zi, ull vv) {
    const ull ABSM = 0x7FFFFFFF7FFFFFFFULL;
    const ull SGN  = 0x8000000080000000ULL;
    const ull CA6 = pk2(0.0000430638f, 0.0000430638f);
    const ull CA5 = pk2(0.0002765672f, 0.0002765672f);
    const ull CA4 = pk2(0.0001520143f, 0.0001520143f);
    const ull CA3 = pk2(0.0092705272f, 0.0092705272f);
    const ull CA2 = pk2(0.0422820123f, 0.0422820123f);
    const ull CA1 = pk2(0.0705230784f, 0.0705230784f);
    const ull ONE2 = pk2(1.0f, 1.0f);

    ull u  = fma2(wx, zi, vv);
    ull ax = u & ABSM;
    ull h  = fma2(CA6, ax, CA5);
    h = fma2(h, ax, CA4);
    h = fma2(h, ax, CA3);
    h = fma2(h, ax, CA2);
    h = fma2(h, ax, CA1);
    ull z = fma2(h, ax, ONE2);
    z = mul2(z, z);
    z = mul2(z, z);
    z = mul2(z, z);
    z = mul2(z, z);                    // z^16
    float f0, f1; upk2(z, f0, f1);
    ull r = pk2(rcpf(f0), rcpf(f1));   // z^-16 (INF -> 0, graceful tail)
    ull upa = add2(u, ax);             // u + |u|
    ull nax = ax ^ SGN;                // -|u|
    return fma2(nax, r, upa);          // (u+|u|) - |u|*r = u*(1+erf(u))
}

// ---------------------------------------------------------------------------
// Kernel 0: BatchNorm over batch for all C*T features; writes xn and first
// patch directly into d_out. Also resets the step barrier counters.
// ---------------------------------------------------------------------------
__global__ void bn0_kernel(const float* __restrict__ x,
                           const float* __restrict__ g0,
                           const float* __restrict__ b0,
                           float* __restrict__ out)
{
    int f = blockIdx.x * blockDim.x + threadIdx.x;
    if (f < STEPS) d_ctr[f] = 0u;
    if (f >= NFEAT) return;
    float v[BB];
    float sum = 0.f;
    #pragma unroll
    for (int b = 0; b < BB; b++) { v[b] = x[b*NFEAT + f]; sum += v[b]; }
    float mu = sum * (1.0f/BB);
    float var = 0.f;
    #pragma unroll
    for (int b = 0; b < BB; b++) { float d = v[b] - mu; var = fmaf(d, d, var); }
    var *= (1.0f/BB);
    float rs = rsqrtf(var + EPS);
    float g = g0[f], bb0 = b0[f];
    int t = f % TT;
    #pragma unroll
    for (int b = 0; b < BB; b++) {
        float y = (v[b] - mu) * rs * g + bb0;
        d_xn[b*NFEAT + f] = y;
        if (t < PATCH) out[b*NFEAT + f] = y;
    }
}

// ---------------------------------------------------------------------------
// Fused step kernel: 576 blocks x 192 threads.
//   A-phase: blocks 0..47 (one channel each) do BN1 -> Wagg -> gelu -> +xw ->
//            BN2 -> t/msg/res, then release d_ctr[s].
//   Barrier: every block spins (1 thread) until d_ctr[s] == 48.
//   B-phase: edge MLP (packed A&S 7.1.28 gelu) + top-3 + softmax + aggregate.
// Deadlock-free: producers are blocks 0..47 (wave-1 on 148 SMs) and never
// wait on consumers; any wave-2 block starts after the counter is complete.
// ---------------------------------------------------------------------------
#define INVR2 0.70710678118654752f

__global__ __launch_bounds__(192, 4) void step_kernel(
    float* __restrict__ out,
    const float* __restrict__ g1, const float* __restrict__ b1,
    const float* __restrict__ g2, const float* __restrict__ b2,
    const float* __restrict__ Wagg, const float* __restrict__ bagg,
    const float* __restrict__ W1, const float* __restrict__ bm1,
    const float* __restrict__ W2, const float* __restrict__ bm2,
    const float* __restrict__ wmsg, const float* __restrict__ bmsg,
    int s)
{
    int blk = blockIdx.x;            // 0..575
    int tid = threadIdx.x;           // 0..191

    __shared__ float  sT[CC], sMsg[CC], sRes[CC];
    __shared__ ulonglong2 sWA[FF];   // {(wx,wx),(w2,w2)}
    __shared__ ulonglong2 sWB[FF];   // {(wy,wy),(bb,bb)}
    __shared__ float  sE[ROWS*CC];   // 768
    __shared__ float  sBn[PATCH*16]; // A-phase scratch

    // Load/pack MLP weights while A-phase / spin proceeds.
    if (tid >= 64 && tid < 128) {
        int f = tid - 64;
        float wx = W1[2*f]   * INVR2;
        float wy = W1[2*f+1] * INVR2;
        float wb = bm1[f]    * INVR2;
        float w2 = W2[f]     * INVR2;
        ulonglong2 wa; wa.x = pk2(wx, wx); wa.y = pk2(w2, w2);
        ulonglong2 wbv; wbv.x = pk2(wy, wy); wbv.y = pk2(wb, wb);
        sWA[f] = wa;
        sWB[f] = wbv;
    }

    // ---------------- A-phase (producer blocks only) ----------------
    if (blk < NPROD) {
        int c = blk;
        int p = tid >> 4;        // 0..11
        int b = tid & 15;        // 0..15

        float v = out[b*NFEAT + c*TT + 12*s + p];

        float sum = v;
        #pragma unroll
        for (int m = 1; m < 16; m <<= 1) sum += __shfl_xor_sync(0xffffffffu, sum, m);
        float mu = sum * (1.0f/16.0f);
        float d = v - mu;
        float q = d * d;
        #pragma unroll
        for (int m = 1; m < 16; m <<= 1) q += __shfl_xor_sync(0xffffffffu, q, m);
        float rs = rsqrtf(q * (1.0f/16.0f) + EPS);
        float bn = d * rs * g1[c*PATCH + p] + b1[c*PATCH + p];
        sBn[p*16 + b] = bn;
        __syncthreads();

        float acc = bagg[p];
        #pragma unroll
        for (int pp = 0; pp < PATCH; pp++)
            acc = fmaf(sBn[pp*16 + b], Wagg[p*PATCH + pp], acc);
        float inp = gelu_exact(acc);
        float res = inp + d_xn[b*NFEAT + c*TT + 12*s + PATCH + p];

        float sum2 = res;
        #pragma unroll
        for (int m = 1; m < 16; m <<= 1) sum2 += __shfl_xor_sync(0xffffffffu, sum2, m);
        float mu2 = sum2 * (1.0f/16.0f);
        float d2 = res - mu2;
        float q2 = d2 * d2;
        #pragma unroll
        for (int m = 1; m < 16; m <<= 1) q2 += __shfl_xor_sync(0xffffffffu, q2, m);
        float rs2 = rsqrtf(q2 * (1.0f/16.0f) + EPS);
        float tv = d2 * rs2 * g2[c*PATCH + p] + b2[c*PATCH + p];

        d_tbuf[b*CP + c*PATCH + p] = tv;
        d_resbuf[b*CP + c*PATCH + p] = res;

        __threadfence();
        __syncthreads();
        if (tid == 0) {
            asm volatile("red.release.gpu.global.add.u32 [%0], %1;"
                         :: "l"(&d_ctr[s]), "r"(1u) : "memory");
        }
    }

    // ---------------- barrier: wait for all 48 producers ----------------
    if (tid == 0) {
        unsigned int vct;
        do {
            asm volatile("ld.acquire.gpu.global.u32 %0, [%1];"
                         : "=r"(vct) : "l"(&d_ctr[s]) : "memory");
            if (vct < NPROD) __nanosleep(64);
        } while (vct < NPROD);
    }
    __syncthreads();
    __threadfence();

    // ---------------- B-phase ----------------
    int bp  = blk / SPLIT;
    int seg = blk % SPLIT;
    int b = bp / PATCH;
    int p = bp % PATCH;

    if (tid < CC) {
        float tv = d_tbuf[b*CP + tid*PATCH + p];
        sT[tid]   = tv;
        sMsg[tid] = fmaf(tv, wmsg[0], bmsg[0]);
        sRes[tid] = d_resbuf[b*CP + tid*PATCH + p];
    }
    __syncthreads();

    float zjv = sT[tid % CC];
    ull zjpk = pk2(zjv, zjv);
    int rbase = tid / CC;            // 0..3
    float bm2v = bm2[0];

    ull zi01 = pk2(sT[seg*ROWS + rbase],     sT[seg*ROWS + rbase + 4]);
    ull zi23 = pk2(sT[seg*ROWS + rbase + 8], sT[seg*ROWS + rbase + 12]);
    ull acc01 = pk2(bm2v, bm2v);
    ull acc23 = acc01;

    #pragma unroll 8
    for (int f = 0; f < FF; f++) {
        ulonglong2 wa = sWA[f];
        ulonglong2 wb = sWB[f];
        ull vv = fma2(wb.x, zjpk, wb.y);      // (wy*zj + bb) duplicated
        acc01 = fma2(wa.y, edge_gelu2(wa.x, zi01, vv), acc01);
        acc23 = fma2(wa.y, edge_gelu2(wa.x, zi23, vv), acc23);
    }

    {
        float e0, e1, e2, e3;
        upk2(acc01, e0, e1);
        upk2(acc23, e2, e3);
        int j = tid % CC;
        sE[(rbase     )*CC + j] = e0;
        sE[(rbase +  4)*CC + j] = e1;
        sE[(rbase +  8)*CC + j] = e2;
        sE[(rbase + 12)*CC + j] = e3;
    }
    __syncthreads();

    // top-3 + softmax + aggregate: one thread per row
    if (tid < ROWS) {
        int i = seg*ROWS + tid;
        const float* row = &sE[tid*CC];
        float v0 = -1e30f, v1 = -1e30f, v2 = -1e30f;
        int   i0 = 0,      i1 = 0,      i2 = 0;
        #pragma unroll 4
        for (int j = 0; j < CC; j++) {
            float e = row[j];
            if (e > v0)      { v2=v1; i2=i1; v1=v0; i1=i0; v0=e; i0=j; }
            else if (e > v1) { v2=v1; i2=i1; v1=e;  i1=j; }
            else if (e > v2) { v2=e;  i2=j; }
        }
        float e1 = expf(v1 - v0), e2 = expf(v2 - v0);
        float inv = 1.0f / (1.0f + e1 + e2);
        float zn = (sMsg[i0] + e1*sMsg[i1] + e2*sMsg[i2]) * inv;
        float o = sRes[i] + ALPHA * zn;
        out[b*NFEAT + i*TT + 12*s + PATCH + p] = o;   // prev for step s+1
    }
}

// ---------------------------------------------------------------------------
extern "C" void kernel_launch(void* const* d_in, const int* in_sizes, int n_in,
                              void* d_out, int out_size)
{
    const float* x    = (const float*)d_in[0];
    const float* g0   = (const float*)d_in[1];
    const float* b0   = (const float*)d_in[2];
    const float* g1   = (const float*)d_in[3];
    const float* b1   = (const float*)d_in[4];
    const float* g2   = (const float*)d_in[5];
    const float* b2   = (const float*)d_in[6];
    const float* Wagg = (const float*)d_in[7];
    const float* bagg = (const float*)d_in[8];
    const float* W1   = (const float*)d_in[9];
    const float* bm1  = (const float*)d_in[10];
    const float* W2   = (const float*)d_in[11];
    const float* bm2  = (const float*)d_in[12];
    const float* wmsg = (const float*)d_in[13];
    const float* bmsg = (const float*)d_in[14];
    float* out = (float*)d_out;

    bn0_kernel<<<(NFEAT + 255)/256, 256>>>(x, g0, b0, out);

    for (int s = 0; s < STEPS; s++) {
        step_kernel<<<NBLK, 192>>>(out, g1, b1, g2, b2, Wagg, bagg,
                                   W1, bm1, W2, bm2, wmsg, bmsg, s);
    }
}

// round 14
// speedup vs baseline: 1.0679x; 1.0085x over previous
#include <cuda_runtime.h>
#include <math.h>

// Problem constants
#define BB 16
#define CC 48
#define TT 96
#define PATCH 12
#define STEPS 7
#define FF 64
#define ALPHA 0.5f
#define EPS 1e-5f
#define NFEAT (CC*TT)    // 4608
#define CP (CC*PATCH)    // 576
#define SPLIT 3
#define ROWS (CC/SPLIT)  // 16
#define NBLK (BB*PATCH*SPLIT)  // 576
#define NPROD CC               // 48 producer blocks

// Scratch (allocation-free rule: __device__ globals)
__device__ float d_xn[BB*NFEAT];
__device__ float d_resbuf[BB*CP];
__device__ float d_tbuf[BB*CP];
__device__ unsigned int d_ctr[STEPS];

// ---------------------------------------------------------------------------
// f32x2 packed helpers (sm_103a)
// ---------------------------------------------------------------------------
typedef unsigned long long ull;

__device__ __forceinline__ ull pk2(float lo, float hi) {
    ull r; asm("mov.b64 %0, {%1, %2};" : "=l"(r) : "f"(lo), "f"(hi)); return r;
}
__device__ __forceinline__ void upk2(ull v, float& lo, float& hi) {
    asm("mov.b64 {%0, %1}, %2;" : "=f"(lo), "=f"(hi) : "l"(v));
}
__device__ __forceinline__ ull fma2(ull a, ull b, ull c) {
    ull d; asm("fma.rn.f32x2 %0, %1, %2, %3;" : "=l"(d) : "l"(a), "l"(b), "l"(c)); return d;
}
__device__ __forceinline__ ull mul2(ull a, ull b) {
    ull d; asm("mul.rn.f32x2 %0, %1, %2;" : "=l"(d) : "l"(a), "l"(b)); return d;
}
__device__ __forceinline__ ull add2(ull a, ull b) {
    ull d; asm("add.rn.f32x2 %0, %1, %2;" : "=l"(d) : "l"(a), "l"(b)); return d;
}
__device__ __forceinline__ float rcpf(float x) {
    float r; asm("rcp.approx.f32 %0, %1;" : "=f"(r) : "f"(x)); return r;
}

__device__ __forceinline__ float gelu_exact(float v) {
    return 0.5f * v * (1.0f + erff(v * 0.70710678118654752f));
}

// A&S 7.1.28: erf(x) = 1 - (1 + a1 x + ... + a6 x^6)^-16, x>=0, |eps|<=3e-7.
// Returns g = u*(1+erf(u)) = (u+|u|) - |u|*z^-16 for packed pair u.
__device__ __forceinline__ ull edge_gelu2(ull wx, ull zi, ull vv) {
    const ull ABSM = 0x7FFFFFFF7FFFFFFFULL;
    const ull SGN  = 0x8000000080000000ULL;
    const ull CA6 = pk2(0.0000430638f, 0.0000430638f);
    const ull CA5 = pk2(0.0002765672f, 0.0002765672f);
    const ull CA4 = pk2(0.0001520143f, 0.0001520143f);
    const ull CA3 = pk2(0.0092705272f, 0.0092705272f);
    const ull CA2 = pk2(0.0422820123f, 0.0422820123f);
    const ull CA1 = pk2(0.0705230784f, 0.0705230784f);
    const ull ONE2 = pk2(1.0f, 1.0f);

    ull u  = fma2(wx, zi, vv);
    ull ax = u & ABSM;
    ull h  = fma2(CA6, ax, CA5);
    h = fma2(h, ax, CA4);
    h = fma2(h, ax, CA3);
    h = fma2(h, ax, CA2);
    h = fma2(h, ax, CA1);
    ull z = fma2(h, ax, ONE2);
    z = mul2(z, z);
    z = mul2(z, z);
    z = mul2(z, z);
    z = mul2(z, z);                    // z^16
    float f0, f1; upk2(z, f0, f1);
    ull r = pk2(rcpf(f0), rcpf(f1));   // z^-16 (INF -> 0, graceful tail)
    ull upa = add2(u, ax);             // u + |u|
    ull nax = ax ^ SGN;                // -|u|
    return fma2(nax, r, upa);          // (u+|u|) - |u|*r = u*(1+erf(u))
}

// ---------------------------------------------------------------------------
// Kernel 0: BatchNorm over batch for all C*T features; writes xn and first
// patch directly into d_out. Also resets the step barrier counters.
// ---------------------------------------------------------------------------
__global__ void bn0_kernel(const float* __restrict__ x,
                           const float* __restrict__ g0,
                           const float* __restrict__ b0,
                           float* __restrict__ out)
{
    int f = blockIdx.x * blockDim.x + threadIdx.x;
    if (f < STEPS) d_ctr[f] = 0u;
    if (f >= NFEAT) return;
    float v[BB];
    float sum = 0.f;
    #pragma unroll
    for (int b = 0; b < BB; b++) { v[b] = x[b*NFEAT + f]; sum += v[b]; }
    float mu = sum * (1.0f/BB);
    float var = 0.f;
    #pragma unroll
    for (int b = 0; b < BB; b++) { float d = v[b] - mu; var = fmaf(d, d, var); }
    var *= (1.0f/BB);
    float rs = rsqrtf(var + EPS);
    float g = g0[f], bb0 = b0[f];
    int t = f % TT;
    #pragma unroll
    for (int b = 0; b < BB; b++) {
        float y = (v[b] - mu) * rs * g + bb0;
        d_xn[b*NFEAT + f] = y;
        if (t < PATCH) out[b*NFEAT + f] = y;
    }
}

// ---------------------------------------------------------------------------
// Fused step kernel: 576 blocks x 192 threads.
//   A-phase: blocks 0..47 (one channel each) do BN1 -> Wagg -> gelu -> +xw ->
//            BN2 -> t/msg/res, then release d_ctr[s].
//   Barrier: every block spins (1 thread) until d_ctr[s] == 48.
//   B-phase: edge MLP (packed A&S 7.1.28 gelu) + top-3 + softmax + aggregate.
// Deadlock-free: producers are blocks 0..47 (wave-1 on 148 SMs) and never
// wait on consumers; any wave-2 block starts after the counter is complete.
// ---------------------------------------------------------------------------
#define INVR2 0.70710678118654752f

__global__ __launch_bounds__(192, 4) void step_kernel(
    float* __restrict__ out,
    const float* __restrict__ g1, const float* __restrict__ b1,
    const float* __restrict__ g2, const float* __restrict__ b2,
    const float* __restrict__ Wagg, const float* __restrict__ bagg,
    const float* __restrict__ W1, const float* __restrict__ bm1,
    const float* __restrict__ W2, const float* __restrict__ bm2,
    const float* __restrict__ wmsg, const float* __restrict__ bmsg,
    int s)
{
    int blk = blockIdx.x;            // 0..575
    int tid = threadIdx.x;           // 0..191

    __shared__ float  sT[CC], sMsg[CC], sRes[CC];
    __shared__ ulonglong2 sWA[FF];   // {(wx,wx),(w2,w2)}
    __shared__ ulonglong2 sWB[FF];   // {(wy,wy),(bb,bb)}
    __shared__ float  sE[ROWS*CC];   // 768
    __shared__ float  sBn[PATCH*16]; // A-phase scratch

    // Load/pack MLP weights while A-phase / spin proceeds.
    if (tid >= 64 && tid < 128) {
        int f = tid - 64;
        float wx = W1[2*f]   * INVR2;
        float wy = W1[2*f+1] * INVR2;
        float wb = bm1[f]    * INVR2;
        float w2 = W2[f]     * INVR2;
        ulonglong2 wa; wa.x = pk2(wx, wx); wa.y = pk2(w2, w2);
        ulonglong2 wbv; wbv.x = pk2(wy, wy); wbv.y = pk2(wb, wb);
        sWA[f] = wa;
        sWB[f] = wbv;
    }

    // ---------------- A-phase (producer blocks only) ----------------
    if (blk < NPROD) {
        int c = blk;
        int p = tid >> 4;        // 0..11
        int b = tid & 15;        // 0..15

        float v = out[b*NFEAT + c*TT + 12*s + p];

        float sum = v;
        #pragma unroll
        for (int m = 1; m < 16; m <<= 1) sum += __shfl_xor_sync(0xffffffffu, sum, m);
        float mu = sum * (1.0f/16.0f);
        float d = v - mu;
        float q = d * d;
        #pragma unroll
        for (int m = 1; m < 16; m <<= 1) q += __shfl_xor_sync(0xffffffffu, q, m);
        float rs = rsqrtf(q * (1.0f/16.0f) + EPS);
        float bn = d * rs * g1[c*PATCH + p] + b1[c*PATCH + p];
        sBn[p*16 + b] = bn;
        __syncthreads();

        float acc = bagg[p];
        #pragma unroll
        for (int pp = 0; pp < PATCH; pp++)
            acc = fmaf(sBn[pp*16 + b], Wagg[p*PATCH + pp], acc);
        float inp = gelu_exact(acc);
        float res = inp + d_xn[b*NFEAT + c*TT + 12*s + PATCH + p];

        float sum2 = res;
        #pragma unroll
        for (int m = 1; m < 16; m <<= 1) sum2 += __shfl_xor_sync(0xffffffffu, sum2, m);
        float mu2 = sum2 * (1.0f/16.0f);
        float d2 = res - mu2;
        float q2 = d2 * d2;
        #pragma unroll
        for (int m = 1; m < 16; m <<= 1) q2 += __shfl_xor_sync(0xffffffffu, q2, m);
        float rs2 = rsqrtf(q2 * (1.0f/16.0f) + EPS);
        float tv = d2 * rs2 * g2[c*PATCH + p] + b2[c*PATCH + p];

        d_tbuf[b*CP + c*PATCH + p] = tv;
        d_resbuf[b*CP + c*PATCH + p] = res;

        __threadfence();
        __syncthreads();
        if (tid == 0) {
            asm volatile("red.release.gpu.global.add.u32 [%0], %1;"
                         :: "l"(&d_ctr[s]), "r"(1u) : "memory");
        }
    }

    // ---------------- barrier: wait for all 48 producers ----------------
    if (tid == 0) {
        unsigned int vct;
        do {
            asm volatile("ld.acquire.gpu.global.u32 %0, [%1];"
                         : "=r"(vct) : "l"(&d_ctr[s]) : "memory");
            if (vct < NPROD) __nanosleep(64);
        } while (vct < NPROD);
    }
    __syncthreads();
    __threadfence();

    // ---------------- B-phase ----------------
    int bp  = blk / SPLIT;
    int seg = blk % SPLIT;
    int b = bp / PATCH;
    int p = bp % PATCH;

    if (tid < CC) {
        float tv = d_tbuf[b*CP + tid*PATCH + p];
        sT[tid]   = tv;
        sMsg[tid] = fmaf(tv, wmsg[0], bmsg[0]);
        sRes[tid] = d_resbuf[b*CP + tid*PATCH + p];
    }
    __syncthreads();

    float zjv = sT[tid % CC];
    ull zjpk = pk2(zjv, zjv);
    int rbase = tid / CC;            // 0..3
    float bm2v = bm2[0];

    ull zi01 = pk2(sT[seg*ROWS + rbase],     sT[seg*ROWS + rbase + 4]);
    ull zi23 = pk2(sT[seg*ROWS + rbase + 8], sT[seg*ROWS + rbase + 12]);
    ull acc01 = pk2(bm2v, bm2v);
    ull acc23 = acc01;

    #pragma unroll 8
    for (int f = 0; f < FF; f++) {
        ulonglong2 wa = sWA[f];
        ulonglong2 wb = sWB[f];
        ull vv = fma2(wb.x, zjpk, wb.y);      // (wy*zj + bb) duplicated
        acc01 = fma2(wa.y, edge_gelu2(wa.x, zi01, vv), acc01);
        acc23 = fma2(wa.y, edge_gelu2(wa.x, zi23, vv), acc23);
    }

    {
        float e0, e1, e2, e3;
        upk2(acc01, e0, e1);
        upk2(acc23, e2, e3);
        int j = tid % CC;
        sE[(rbase     )*CC + j] = e0;
        sE[(rbase +  4)*CC + j] = e1;
        sE[(rbase +  8)*CC + j] = e2;
        sE[(rbase + 12)*CC + j] = e3;
    }
    __syncthreads();

    // top-3 + softmax + aggregate: one thread per row
    if (tid < ROWS) {
        int i = seg*ROWS + tid;
        const float* row = &sE[tid*CC];
        float v0 = -1e30f, v1 = -1e30f, v2 = -1e30f;
        int   i0 = 0,      i1 = 0,      i2 = 0;
        #pragma unroll 4
        for (int j = 0; j < CC; j++) {
            float e = row[j];
            if (e > v0)      { v2=v1; i2=i1; v1=v0; i1=i0; v0=e; i0=j; }
            else if (e > v1) { v2=v1; i2=i1; v1=e;  i1=j; }
            else if (e > v2) { v2=e;  i2=j; }
        }
        float e1 = expf(v1 - v0), e2 = expf(v2 - v0);
        float inv = 1.0f / (1.0f + e1 + e2);
        float zn = (sMsg[i0] + e1*sMsg[i1] + e2*sMsg[i2]) * inv;
        float o = sRes[i] + ALPHA * zn;
        out[b*NFEAT + i*TT + 12*s + PATCH + p] = o;   // prev for step s+1
    }
}

// ---------------------------------------------------------------------------
extern "C" void kernel_launch(void* const* d_in, const int* in_sizes, int n_in,
                              void* d_out, int out_size)
{
    const float* x    = (const float*)d_in[0];
    const float* g0   = (const float*)d_in[1];
    const float* b0   = (const float*)d_in[2];
    const float* g1   = (const float*)d_in[3];
    const float* b1   = (const float*)d_in[4];
    const float* g2   = (const float*)d_in[5];
    const float* b2   = (const float*)d_in[6];
    const float* Wagg = (const float*)d_in[7];
    const float* bagg = (const float*)d_in[8];
    const float* W1   = (const float*)d_in[9];
    const float* bm1  = (const float*)d_in[10];
    const float* W2   = (const float*)d_in[11];
    const float* bm2  = (const float*)d_in[12];
    const float* wmsg = (const float*)d_in[13];
    const float* bmsg = (const float*)d_in[14];
    float* out = (float*)d_out;

    bn0_kernel<<<(NFEAT + 255)/256, 256>>>(x, g0, b0, out);

    for (int s = 0; s < STEPS; s++) {
        step_kernel<<<NBLK, 192>>>(out, g1, b1, g2, b2, Wagg, bagg,
                                   W1, bm1, W2, bm2, wmsg, bmsg, s);
    }
}